// round 13
// baseline (speedup 1.0000x reference)
#include <cuda_runtime.h>
#include <cuda_bf16.h>
#include <cuda_fp16.h>
#include <math.h>
#include <stdint.h>

// ---------------------------------------------------------------------------
// Mamba2 block: fp16 HMMA GEMMs (64x64 warp tiles) + hierarchical scan
// ---------------------------------------------------------------------------

#define Bdim 4
#define Sdim 4096
#define Hdim 1024
#define Mrows (Bdim * Sdim)        // 16384
#define BSH   (Mrows * Hdim)
#define CHUNKS 256
#define CLEN   16
#define NSUP   16
#define SUPC   16

// -------------------- scratch (static __device__, no allocs) ---------------
__device__ __half g_x1[BSH];
__device__ __half g_y1[BSH];
__device__ __half g_w51[5 * Hdim * Hdim];
__device__ __half g_wo1[Hdim * Hdim];
__device__ __half g_cont[BSH];
__device__ __half g_ret[BSH];
__device__ __half g_wg[BSH];
__device__ __half g_rg[BSH];
__device__ __half g_sk[BSH];
__device__ float g_Ac[Bdim * CHUNKS * Hdim];
__device__ float g_Bc[Bdim * CHUNKS * Hdim];
__device__ float g_Ss[Bdim * CHUNKS * Hdim];
__device__ float g_As[Bdim * NSUP * Hdim];
__device__ float g_Bs[Bdim * NSUP * Hdim];
__device__ float g_Sss[Bdim * NSUP * Hdim];
__device__ int   g_mask_mode;
__device__ float g_fs_dummy[Bdim * Hdim];

// -------------------- fast activations (MUFU) -------------------------------
__device__ __forceinline__ float fast_ex2(float x) {
    float r;
    asm("ex2.approx.f32 %0, %1;" : "=f"(r) : "f"(x));
    return r;
}
__device__ __forceinline__ float fast_rcp(float x) {
    float r;
    asm("rcp.approx.f32 %0, %1;" : "=f"(r) : "f"(x));
    return r;
}
#define L2E 1.4426950408889634f
__device__ __forceinline__ float fast_sigmoid(float x) {
    return fast_rcp(1.0f + fast_ex2(-L2E * x));
}
__device__ __forceinline__ float fast_tanh(float x) {
    float xc = fminf(fmaxf(x, -10.0f), 10.0f);
    float t = fast_ex2(2.0f * L2E * xc);
    return (t - 1.0f) * fast_rcp(t + 1.0f);
}

// -------------------- mask dtype detection ---------------------------------
__global__ void detect_mask_kernel(const unsigned char* __restrict__ mb, int n) {
    __shared__ int cflag[4];
    int t = threadIdx.x;
    if (t < 4) cflag[t] = 0;
    __syncthreads();
    for (int i = t; i < n; i += blockDim.x)
        if (mb[i]) atomicOr(&cflag[i & 3], 1);
    __syncthreads();
    if (t == 0) {
        int c0 = cflag[0], c1 = cflag[1], c2 = cflag[2], c3 = cflag[3];
        int mode = 0;
        if (c0 | c1 | c2 | c3) {
            if (c0 && !c1 && !c2 && !c3) mode = 1;
            else if (!c0 && !c1 && (c2 | c3)) mode = 2;
        }
        g_mask_mode = mode;
    }
}

__device__ __forceinline__ float mask_at(const void* mraw, int i, int mode) {
    if (mode == 1) return ((const int*)mraw)[i] != 0 ? 1.0f : 0.0f;
    if (mode == 2) return ((const float*)mraw)[i] != 0.0f ? 1.0f : 0.0f;
    return ((const unsigned char*)mraw)[i] ? 1.0f : 0.0f;
}

// -------------------- fused fp32 -> fp16 conversion -------------------------
struct CvtAllArgs { const float* src[22]; __half* dst[22]; };
__global__ void cvt_all_kernel(CvtAllArgs a) {
    int job = blockIdx.x >> 10;
    int i = ((blockIdx.x & 1023) * blockDim.x + threadIdx.x) * 4;
    const float* in = a.src[job];
    __half* o = a.dst[job];
    float4 v = *(const float4*)(in + i);
    ((__half2*)(o + i))[0] = __halves2half2(__float2half_rn(v.x), __float2half_rn(v.y));
    ((__half2*)(o + i))[1] = __halves2half2(__float2half_rn(v.z), __float2half_rn(v.w));
}

// -------------------- PTX helpers ------------------------------------------
__device__ __forceinline__ uint32_t su32(const void* p) {
    uint32_t a;
    asm("{ .reg .u64 t; cvta.to.shared.u64 t, %1; cvt.u32.u64 %0, t; }"
        : "=r"(a) : "l"(p));
    return a;
}
__device__ __forceinline__ void cpa16(uint32_t s, const void* g) {
    asm volatile("cp.async.cg.shared.global [%0], [%1], 16;" :: "r"(s), "l"(g));
}
__device__ __forceinline__ void cpa_commit() {
    asm volatile("cp.async.commit_group;" ::: "memory");
}
__device__ __forceinline__ void cpa_wait1() {
    asm volatile("cp.async.wait_group 1;" ::: "memory");
}
__device__ __forceinline__ void cpa_wait0() {
    asm volatile("cp.async.wait_group 0;" ::: "memory");
}
__device__ __forceinline__ void ldm_x4(uint32_t* r, uint32_t addr) {
    asm volatile("ldmatrix.sync.aligned.m8n8.x4.shared.b16 {%0,%1,%2,%3}, [%4];"
                 : "=r"(r[0]), "=r"(r[1]), "=r"(r[2]), "=r"(r[3]) : "r"(addr));
}
__device__ __forceinline__ void mma_f16(float* d, const uint32_t* a,
                                        const uint32_t* b) {
    asm volatile(
        "mma.sync.aligned.m16n8k16.row.col.f32.f16.f16.f32 "
        "{%0,%1,%2,%3}, {%4,%5,%6,%7}, {%8,%9}, {%0,%1,%2,%3};"
        : "+f"(d[0]), "+f"(d[1]), "+f"(d[2]), "+f"(d[3])
        : "r"(a[0]), "r"(a[1]), "r"(a[2]), "r"(a[3]), "r"(b[0]), "r"(b[1]));
}

// -------------------- GEMM: 64x64 warp tiles, 128 threads -------------------
#define TILE_BYTES 16384
#define STAGE_BYTES 32768
#define SMEM_TOTAL (3 * STAGE_BYTES)   // 98304
#define NSTAGES (Hdim / 64)            // 16

struct GArgs {
    const __half *A1, *W1;
    void*        outp[5];
    const float* bias[5];
    int          act[5];
    int          half_out[5];
};

__device__ __forceinline__ uint32_t sw128(uint32_t base, int row, int chunk) {
    return base + row * 128 + ((chunk ^ (row & 7)) << 4);
}

__global__ __launch_bounds__(128, 2)
void gemm_mma_kernel(GArgs ga) {
    extern __shared__ char smem[];
    uint32_t sb = su32(smem);
    int tid = threadIdx.x;
    int wid = tid >> 5, lane = tid & 31;
    int wm = wid >> 1, wn = wid & 1;           // 2 x 2 warp grid
    int m0 = wm * 64, n0 = wn * 64;            // warp tile 64x64

    int mBase = blockIdx.y * 128;
    int nBase = blockIdx.x * 128;
    const __half* pA = ga.A1 + (size_t)mBase * Hdim;
    const __half* pW = ga.W1 + (size_t)nBase * Hdim;

    float acc[4][8][4];
#pragma unroll
    for (int i = 0; i < 4; i++)
#pragma unroll
        for (int j = 0; j < 8; j++)
#pragma unroll
            for (int e = 0; e < 4; e++) acc[i][j][e] = 0.0f;

    auto load_stage = [&](int s) {
        uint32_t so = sb + (s % 3) * STAGE_BYTES;
        int k0 = s * 64;
#pragma unroll
        for (int i = 0; i < 16; i++) {
            int c = tid + i * 128;             // 0..2047
            int T = c >> 10;                   // 0=A 1=W
            int ct = c & 1023;
            int row = ct >> 3, col = ct & 7;
            const __half* src = T ? pW : pA;
            cpa16(sw128(so + T * TILE_BYTES, row, col),
                  src + (size_t)row * Hdim + k0 + col * 8);
        }
        cpa_commit();
    };

    load_stage(0);
    load_stage(1);

    int aRow = (lane & 15);
    int aKC  = (lane >> 4);
    int bRow = (lane & 7) + ((lane >> 4) << 3);
    int bKC  = (lane >> 3) & 1;

    for (int s = 0; s < NSTAGES; s++) {
        if (s + 1 < NSTAGES) cpa_wait1();
        else cpa_wait0();
        __syncthreads();
        if (s + 2 < NSTAGES) load_stage(s + 2);

        uint32_t so = sb + (s % 3) * STAGE_BYTES;
        uint32_t tA = so;
        uint32_t tW = so + TILE_BYTES;

#pragma unroll
        for (int kk = 0; kk < 4; kk++) {
            int kc = kk * 2;
            uint32_t b1[16];
#pragma unroll
            for (int half = 0; half < 4; half++)
                ldm_x4(b1 + half * 4, sw128(tW, n0 + half * 16 + bRow, kc + bKC));
#pragma unroll
            for (int mf = 0; mf < 4; mf++) {
                uint32_t a[4];
                ldm_x4(a, sw128(tA, m0 + mf * 16 + aRow, kc + aKC));
#pragma unroll
                for (int nf = 0; nf < 8; nf++)
                    mma_f16(acc[mf][nf], a, b1 + (nf >> 1) * 4 + (nf & 1) * 2);
            }
        }
    }

    int p = nBase >> 10;
    const float* __restrict__ bias = ga.bias[p];
    int act = ga.act[p];
    int hout = ga.half_out[p];
    int ocol0 = (nBase & 1023) + n0;

#pragma unroll
    for (int mf = 0; mf < 4; mf++) {
#pragma unroll
        for (int rh = 0; rh < 2; rh++) {
            int m = mBase + m0 + mf * 16 + (lane >> 2) + rh * 8;
#pragma unroll
            for (int nf = 0; nf < 8; nf++) {
                int col = ocol0 + nf * 8 + (lane & 3) * 2;
                float v0 = acc[mf][nf][rh * 2 + 0];
                float v1 = acc[mf][nf][rh * 2 + 1];
                if (act == 1) {
                    v0 = fast_tanh(v0);
                    v1 = fast_tanh(v1);
                } else if (act == 2) {
                    v0 = fast_sigmoid(v0 + bias[col]);
                    v1 = fast_sigmoid(v1 + bias[col + 1]);
                }
                if (hout) {
                    __half* op = (__half*)ga.outp[p];
                    *(__half2*)(op + (size_t)m * Hdim + col) =
                        __halves2half2(__float2half_rn(v0), __float2half_rn(v1));
                } else {
                    float* op = (float*)ga.outp[p];
                    *(float2*)(op + (size_t)m * Hdim + col) = make_float2(v0, v1);
                }
            }
        }
    }
}

// -------------------- vector helpers ---------------------------------------
__device__ __forceinline__ void unpack8(uint4 u, float* f) {
    __half2* h = (__half2*)&u;
#pragma unroll
    for (int q = 0; q < 4; q++) {
        float2 t = __half22float2(h[q]);
        f[2 * q] = t.x;
        f[2 * q + 1] = t.y;
    }
}
__device__ __forceinline__ uint4 pack8(const float* f) {
    uint4 u;
    __half2* h = (__half2*)&u;
#pragma unroll
    for (int q = 0; q < 4; q++)
        h[q] = __halves2half2(__float2half_rn(f[2 * q]), __float2half_rn(f[2 * q + 1]));
    return u;
}
__device__ __forceinline__ void ld8f(const float* p, float* f) {
    float4 u0 = *(const float4*)p;
    float4 u1 = *(const float4*)(p + 4);
    f[0] = u0.x; f[1] = u0.y; f[2] = u0.z; f[3] = u0.w;
    f[4] = u1.x; f[5] = u1.y; f[6] = u1.z; f[7] = u1.w;
}
__device__ __forceinline__ void st8f(float* p, const float* f) {
    *(float4*)p = make_float4(f[0], f[1], f[2], f[3]);
    *(float4*)(p + 4) = make_float4(f[4], f[5], f[6], f[7]);
}

// -------------------- hierarchical chunked scan -----------------------------
__global__ void scan_stage1(const void* __restrict__ mraw) {
    int id = blockIdx.x * blockDim.x + threadIdx.x;
    int h8 = (id & 127) * 8;
    int j  = (id >> 7) & (CHUNKS - 1);
    int b  = id >> 15;
    int mode = g_mask_mode;
    float A[8], Bc[8];
#pragma unroll
    for (int e = 0; e < 8; e++) { A[e] = 1.0f; Bc[e] = 0.0f; }
    size_t base = (size_t)b * Sdim * Hdim + h8;
    int s0 = j * CLEN;
#pragma unroll
    for (int t = 0; t < CLEN; t++) {
        int s = s0 + t;
        size_t idx = base + (size_t)s * Hdim;
        float a[8], w[8], c[8];
        unpack8(*(const uint4*)(g_ret + idx), a);
        unpack8(*(const uint4*)(g_wg + idx), w);
        unpack8(*(const uint4*)(g_cont + idx), c);
        float m = mask_at(mraw, b * Sdim + s, mode);
#pragma unroll
        for (int e = 0; e < 8; e++) {
            float aa = 1.0f + m * (a[e] - 1.0f);
            float bb = m * ((1.0f - a[e]) * w[e] * c[e]);
            A[e] *= aa;
            Bc[e] = fmaf(aa, Bc[e], bb);
        }
    }
    int cidx = (b * CHUNKS + j) * Hdim + h8;
    st8f(g_Ac + cidx, A);
    st8f(g_Bc + cidx, Bc);
}

__global__ void scan_stage2a() {
    int id = blockIdx.x * blockDim.x + threadIdx.x;
    int h8 = (id & 127) * 8;
    int sc = (id >> 7) & (NSUP - 1);
    int b  = id >> 11;
    float A[8], Bv[8];
#pragma unroll
    for (int e = 0; e < 8; e++) { A[e] = 1.0f; Bv[e] = 0.0f; }
#pragma unroll
    for (int c = 0; c < SUPC; c++) {
        int j = sc * SUPC + c;
        int cidx = (b * CHUNKS + j) * Hdim + h8;
        float Ac[8], Bc[8];
        ld8f(g_Ac + cidx, Ac);
        ld8f(g_Bc + cidx, Bc);
#pragma unroll
        for (int e = 0; e < 8; e++) {
            Bv[e] = fmaf(Ac[e], Bv[e], Bc[e]);
            A[e] *= Ac[e];
        }
    }
    int sidx = (b * NSUP + sc) * Hdim + h8;
    st8f(g_As + sidx, A);
    st8f(g_Bs + sidx, Bv);
}

__global__ void scan_stage2b(const float* __restrict__ state,
                             float* __restrict__ fs_out) {
    int id = blockIdx.x * blockDim.x + threadIdx.x;
    int h8 = (id & 127) * 8;
    int b  = id >> 7;
    float st[8];
    ld8f(state + b * Hdim + h8, st);
#pragma unroll
    for (int sc = 0; sc < NSUP; sc++) {
        int sidx = (b * NSUP + sc) * Hdim + h8;
        st8f(g_Sss + sidx, st);
        float A[8], Bv[8];
        ld8f(g_As + sidx, A);
        ld8f(g_Bs + sidx, Bv);
#pragma unroll
        for (int e = 0; e < 8; e++) st[e] = fmaf(A[e], st[e], Bv[e]);
    }
    st8f(fs_out + b * Hdim + h8, st);
}

__global__ void scan_stage2c() {
    int id = blockIdx.x * blockDim.x + threadIdx.x;
    int h8 = (id & 127) * 8;
    int sc = (id >> 7) & (NSUP - 1);
    int b  = id >> 11;
    float st[8];
    ld8f(g_Sss + (b * NSUP + sc) * Hdim + h8, st);
#pragma unroll
    for (int c = 0; c < SUPC; c++) {
        int j = sc * SUPC + c;
        int cidx = (b * CHUNKS + j) * Hdim + h8;
        st8f(g_Ss + cidx, st);
        float Ac[8], Bc[8];
        ld8f(g_Ac + cidx, Ac);
        ld8f(g_Bc + cidx, Bc);
#pragma unroll
        for (int e = 0; e < 8; e++) st[e] = fmaf(Ac[e], st[e], Bc[e]);
    }
}

__global__ void scan_stage3(const void* __restrict__ mraw) {
    int id = blockIdx.x * blockDim.x + threadIdx.x;
    int h8 = (id & 127) * 8;
    int j  = (id >> 7) & (CHUNKS - 1);
    int b  = id >> 15;
    int mode = g_mask_mode;
    float st[8];
    ld8f(g_Ss + (b * CHUNKS + j) * Hdim + h8, st);
    size_t base = (size_t)b * Sdim * Hdim + h8;
    int s0 = j * CLEN;
#pragma unroll
    for (int t = 0; t < CLEN; t++) {
        int s = s0 + t;
        size_t idx = base + (size_t)s * Hdim;
        float a[8], w[8], c[8], r[8], k[8], y[8];
        unpack8(*(const uint4*)(g_ret + idx), a);
        unpack8(*(const uint4*)(g_wg + idx), w);
        unpack8(*(const uint4*)(g_cont + idx), c);
        unpack8(*(const uint4*)(g_rg + idx), r);
        unpack8(*(const uint4*)(g_sk + idx), k);
        float m = mask_at(mraw, b * Sdim + s, mode);
#pragma unroll
        for (int e = 0; e < 8; e++) {
            float aa = 1.0f + m * (a[e] - 1.0f);
            float bb = m * ((1.0f - a[e]) * w[e] * c[e]);
            st[e] = fmaf(aa, st[e], bb);
            y[e] = m * fmaf(r[e], st[e], k[e]);
        }
        *(uint4*)(g_y1 + idx) = pack8(y);
    }
}

// -------------------- launch -----------------------------------------------
extern "C" void kernel_launch(void* const* d_in, const int* in_sizes, int n_in,
                              void* d_out, int out_size) {
    const float* x     = (const float*)d_in[0];
    const float* state = (const float*)d_in[1];
    const void*  mask  = d_in[2];
    const float* W_in  = (const float*)d_in[3];
    const float* W_a   = (const float*)d_in[4];
    const float* b_a   = (const float*)d_in[5];
    const float* W_b   = (const float*)d_in[6];
    const float* b_b   = (const float*)d_in[7];
    const float* W_c   = (const float*)d_in[8];
    const float* b_c   = (const float*)d_in[9];
    const float* W_d   = (const float*)d_in[10];
    const float* W_out = (const float*)d_in[11];
    float* out = (float*)d_out;

    __half *p_x1, *p_y1, *p_w51, *p_wo1, *p_cont, *p_ret, *p_wg, *p_rg, *p_sk;
    float *p_fsdummy;
    cudaGetSymbolAddress((void**)&p_x1,  g_x1);
    cudaGetSymbolAddress((void**)&p_y1,  g_y1);
    cudaGetSymbolAddress((void**)&p_w51, g_w51);
    cudaGetSymbolAddress((void**)&p_wo1, g_wo1);
    cudaGetSymbolAddress((void**)&p_cont, g_cont);
    cudaGetSymbolAddress((void**)&p_ret,  g_ret);
    cudaGetSymbolAddress((void**)&p_wg,   g_wg);
    cudaGetSymbolAddress((void**)&p_rg,   g_rg);
    cudaGetSymbolAddress((void**)&p_sk,   g_sk);
    cudaGetSymbolAddress((void**)&p_fsdummy, g_fs_dummy);

    cudaFuncSetAttribute(gemm_mma_kernel,
                         cudaFuncAttributeMaxDynamicSharedMemorySize, SMEM_TOTAL);

    detect_mask_kernel<<<1, 256>>>((const unsigned char*)mask, Mrows);

    const size_t WN = (size_t)Hdim * Hdim;
    CvtAllArgs ca;
    for (int q = 0; q < 16; q++) {
        ca.src[q] = x + q * WN;
        ca.dst[q] = p_x1 + q * WN;
    }
    ca.src[16] = W_in;  ca.dst[16] = p_w51 + 0 * WN;
    ca.src[17] = W_a;   ca.dst[17] = p_w51 + 1 * WN;
    ca.src[18] = W_b;   ca.dst[18] = p_w51 + 2 * WN;
    ca.src[19] = W_c;   ca.dst[19] = p_w51 + 3 * WN;
    ca.src[20] = W_d;   ca.dst[20] = p_w51 + 4 * WN;
    ca.src[21] = W_out; ca.dst[21] = p_wo1;
    cvt_all_kernel<<<22 * 1024, 256>>>(ca);

    // Phase 1: fused 5-projection GEMM
    GArgs g1;
    g1.A1 = p_x1; g1.W1 = p_w51;
    g1.outp[0] = p_cont; g1.outp[1] = p_ret; g1.outp[2] = p_wg;
    g1.outp[3] = p_rg;   g1.outp[4] = p_sk;
    g1.bias[0] = nullptr; g1.bias[1] = b_a; g1.bias[2] = b_b;
    g1.bias[3] = b_c;     g1.bias[4] = nullptr;
    g1.act[0] = 1; g1.act[1] = 2; g1.act[2] = 2; g1.act[3] = 2; g1.act[4] = 0;
    g1.half_out[0] = 1; g1.half_out[1] = 1; g1.half_out[2] = 1;
    g1.half_out[3] = 1; g1.half_out[4] = 1;
    gemm_mma_kernel<<<dim3(40, 128), 128, SMEM_TOTAL>>>(g1);

    // Phase 2: hierarchical chunked scan
    float* fsPtr = (out_size >= BSH + Bdim * Hdim) ? (out + BSH) : p_fsdummy;
    scan_stage1<<<512, 256>>>(mask);
    scan_stage2a<<<32, 256>>>();
    scan_stage2b<<<2, 256>>>(state, fsPtr);
    scan_stage2c<<<32, 256>>>();
    scan_stage3<<<512, 256>>>(mask);

    // Phase 3: output GEMM
    GArgs g2;
    g2.A1 = p_y1; g2.W1 = p_wo1;
    for (int i = 0; i < 5; i++) {
        g2.outp[i] = out; g2.bias[i] = nullptr; g2.act[i] = 0; g2.half_out[i] = 0;
    }
    gemm_mma_kernel<<<dim3(8, 128), 128, SMEM_TOTAL>>>(g2);
}

// round 14
// speedup vs baseline: 1.6072x; 1.6072x over previous
#include <cuda_runtime.h>
#include <cuda_bf16.h>
#include <cuda_fp16.h>
#include <math.h>
#include <stdint.h>

// ---------------------------------------------------------------------------
// Mamba2 block: single-product fp16 HMMA GEMMs (64x32 warp tiles, 256thr,
// 2 CTA/SM, 3-stage cp.async) + hierarchical vectorized scan. R12 config.
// ---------------------------------------------------------------------------

#define Bdim 4
#define Sdim 4096
#define Hdim 1024
#define Mrows (Bdim * Sdim)        // 16384
#define BSH   (Mrows * Hdim)
#define CHUNKS 256
#define CLEN   16
#define NSUP   16
#define SUPC   16

// -------------------- scratch (static __device__, no allocs) ---------------
__device__ __half g_x1[BSH];
__device__ __half g_y1[BSH];
__device__ __half g_w51[5 * Hdim * Hdim];
__device__ __half g_wo1[Hdim * Hdim];
__device__ __half g_cont[BSH];
__device__ __half g_ret[BSH];
__device__ __half g_wg[BSH];
__device__ __half g_rg[BSH];
__device__ __half g_sk[BSH];
__device__ float g_Ac[Bdim * CHUNKS * Hdim];
__device__ float g_Bc[Bdim * CHUNKS * Hdim];
__device__ float g_Ss[Bdim * CHUNKS * Hdim];
__device__ float g_As[Bdim * NSUP * Hdim];
__device__ float g_Bs[Bdim * NSUP * Hdim];
__device__ float g_Sss[Bdim * NSUP * Hdim];
__device__ int   g_mask_mode;
__device__ float g_fs_dummy[Bdim * Hdim];

// -------------------- fast activations (MUFU) -------------------------------
__device__ __forceinline__ float fast_ex2(float x) {
    float r;
    asm("ex2.approx.f32 %0, %1;" : "=f"(r) : "f"(x));
    return r;
}
__device__ __forceinline__ float fast_rcp(float x) {
    float r;
    asm("rcp.approx.f32 %0, %1;" : "=f"(r) : "f"(x));
    return r;
}
#define L2E 1.4426950408889634f
__device__ __forceinline__ float fast_sigmoid(float x) {
    return fast_rcp(1.0f + fast_ex2(-L2E * x));
}
__device__ __forceinline__ float fast_tanh(float x) {
    float xc = fminf(fmaxf(x, -10.0f), 10.0f);
    float t = fast_ex2(2.0f * L2E * xc);
    return (t - 1.0f) * fast_rcp(t + 1.0f);
}

__device__ __forceinline__ float mask_at(const void* mraw, int i, int mode) {
    if (mode == 1) return ((const int*)mraw)[i] != 0 ? 1.0f : 0.0f;
    if (mode == 2) return ((const float*)mraw)[i] != 0.0f ? 1.0f : 0.0f;
    return ((const unsigned char*)mraw)[i] ? 1.0f : 0.0f;
}

// -------------------- fused conversions + mask detection --------------------
// Blocks 0..22527: fp32->fp16 conversion jobs (22 x 1M elements).
// Block 22528: mask dtype detection.
struct CvtAllArgs {
    const float* src[22];
    __half* dst[22];
    const unsigned char* mask;
    int mask_n;
};
__global__ void cvt_all_kernel(CvtAllArgs a) {
    if (blockIdx.x == 22 * 1024) {
        __shared__ int cflag[4];
        int t = threadIdx.x;
        if (t < 4) cflag[t] = 0;
        __syncthreads();
        for (int i = t; i < a.mask_n; i += blockDim.x)
            if (a.mask[i]) atomicOr(&cflag[i & 3], 1);
        __syncthreads();
        if (t == 0) {
            int c0 = cflag[0], c1 = cflag[1], c2 = cflag[2], c3 = cflag[3];
            int mode = 0;
            if (c0 | c1 | c2 | c3) {
                if (c0 && !c1 && !c2 && !c3) mode = 1;
                else if (!c0 && !c1 && (c2 | c3)) mode = 2;
            }
            g_mask_mode = mode;
        }
        return;
    }
    int job = blockIdx.x >> 10;
    int i = ((blockIdx.x & 1023) * blockDim.x + threadIdx.x) * 4;
    const float* in = a.src[job];
    __half* o = a.dst[job];
    float4 v = *(const float4*)(in + i);
    ((__half2*)(o + i))[0] = __halves2half2(__float2half_rn(v.x), __float2half_rn(v.y));
    ((__half2*)(o + i))[1] = __halves2half2(__float2half_rn(v.z), __float2half_rn(v.w));
}

// -------------------- PTX helpers ------------------------------------------
__device__ __forceinline__ uint32_t su32(const void* p) {
    uint32_t a;
    asm("{ .reg .u64 t; cvta.to.shared.u64 t, %1; cvt.u32.u64 %0, t; }"
        : "=r"(a) : "l"(p));
    return a;
}
__device__ __forceinline__ void cpa16(uint32_t s, const void* g) {
    asm volatile("cp.async.cg.shared.global [%0], [%1], 16;" :: "r"(s), "l"(g));
}
__device__ __forceinline__ void cpa_commit() {
    asm volatile("cp.async.commit_group;" ::: "memory");
}
__device__ __forceinline__ void cpa_wait1() {
    asm volatile("cp.async.wait_group 1;" ::: "memory");
}
__device__ __forceinline__ void cpa_wait0() {
    asm volatile("cp.async.wait_group 0;" ::: "memory");
}
__device__ __forceinline__ void ldm_x4(uint32_t* r, uint32_t addr) {
    asm volatile("ldmatrix.sync.aligned.m8n8.x4.shared.b16 {%0,%1,%2,%3}, [%4];"
                 : "=r"(r[0]), "=r"(r[1]), "=r"(r[2]), "=r"(r[3]) : "r"(addr));
}
__device__ __forceinline__ void mma_f16(float* d, const uint32_t* a,
                                        const uint32_t* b) {
    asm volatile(
        "mma.sync.aligned.m16n8k16.row.col.f32.f16.f16.f32 "
        "{%0,%1,%2,%3}, {%4,%5,%6,%7}, {%8,%9}, {%0,%1,%2,%3};"
        : "+f"(d[0]), "+f"(d[1]), "+f"(d[2]), "+f"(d[3])
        : "r"(a[0]), "r"(a[1]), "r"(a[2]), "r"(a[3]), "r"(b[0]), "r"(b[1]));
}

// -------------------- GEMM: 64x32 warp tiles, 256 threads, 2 CTA/SM ---------
#define TILE_BYTES 16384
#define STAGE_BYTES 32768
#define SMEM_TOTAL (3 * STAGE_BYTES)   // 98304
#define NSTAGES (Hdim / 64)            // 16

struct GArgs {
    const __half *A1, *W1;
    void*        outp[5];
    const float* bias[5];
    int          act[5];
    int          half_out[5];
};

__device__ __forceinline__ uint32_t sw128(uint32_t base, int row, int chunk) {
    return base + row * 128 + ((chunk ^ (row & 7)) << 4);
}

__global__ __launch_bounds__(256, 2)
void gemm_mma_kernel(GArgs ga) {
    extern __shared__ char smem[];
    uint32_t sb = su32(smem);
    int tid = threadIdx.x;
    int wid = tid >> 5, lane = tid & 31;
    int wm = wid >> 2, wn = wid & 3;           // 2 x 4 warp grid
    int m0 = wm * 64, n0 = wn * 32;            // warp tile 64x32

    int mBase = blockIdx.y * 128;
    int nBase = blockIdx.x * 128;
    const __half* pA = ga.A1 + (size_t)mBase * Hdim;
    const __half* pW = ga.W1 + (size_t)nBase * Hdim;

    float acc[4][4][4];
#pragma unroll
    for (int i = 0; i < 4; i++)
#pragma unroll
        for (int j = 0; j < 4; j++)
#pragma unroll
            for (int e = 0; e < 4; e++) acc[i][j][e] = 0.0f;

    auto load_stage = [&](int s) {
        uint32_t so = sb + (s % 3) * STAGE_BYTES;
        int k0 = s * 64;
#pragma unroll
        for (int i = 0; i < 8; i++) {
            int c = tid + i * 256;
            int T = c >> 10;
            int ct = c & 1023;
            int row = ct >> 3, col = ct & 7;
            const __half* src = T ? pW : pA;
            cpa16(sw128(so + T * TILE_BYTES, row, col),
                  src + (size_t)row * Hdim + k0 + col * 8);
        }
        cpa_commit();
    };

    load_stage(0);
    load_stage(1);

    int aRow = (lane & 15);
    int aKC  = (lane >> 4);
    int bRow = (lane & 7) + ((lane >> 4) << 3);
    int bKC  = (lane >> 3) & 1;

    for (int s = 0; s < NSTAGES; s++) {
        if (s + 1 < NSTAGES) cpa_wait1();
        else cpa_wait0();
        __syncthreads();
        if (s + 2 < NSTAGES) load_stage(s + 2);

        uint32_t so = sb + (s % 3) * STAGE_BYTES;
        uint32_t tA = so;
        uint32_t tW = so + TILE_BYTES;

#pragma unroll
        for (int kk = 0; kk < 4; kk++) {
            int kc = kk * 2;
            uint32_t b1[8];
#pragma unroll
            for (int half = 0; half < 2; half++)
                ldm_x4(b1 + half * 4, sw128(tW, n0 + half * 16 + bRow, kc + bKC));
#pragma unroll
            for (int mf = 0; mf < 4; mf++) {
                uint32_t a[4];
                ldm_x4(a, sw128(tA, m0 + mf * 16 + aRow, kc + aKC));
#pragma unroll
                for (int nf = 0; nf < 4; nf++)
                    mma_f16(acc[mf][nf], a, b1 + (nf >> 1) * 4 + (nf & 1) * 2);
            }
        }
    }

    int p = nBase >> 10;
    const float* __restrict__ bias = ga.bias[p];
    int act = ga.act[p];
    int hout = ga.half_out[p];
    int ocol0 = (nBase & 1023) + n0;

#pragma unroll
    for (int mf = 0; mf < 4; mf++) {
#pragma unroll
        for (int rh = 0; rh < 2; rh++) {
            int m = mBase + m0 + mf * 16 + (lane >> 2) + rh * 8;
#pragma unroll
            for (int nf = 0; nf < 4; nf++) {
                int col = ocol0 + nf * 8 + (lane & 3) * 2;
                float v0 = acc[mf][nf][rh * 2 + 0];
                float v1 = acc[mf][nf][rh * 2 + 1];
                if (act == 1) {
                    v0 = fast_tanh(v0);
                    v1 = fast_tanh(v1);
                } else if (act == 2) {
                    v0 = fast_sigmoid(v0 + bias[col]);
                    v1 = fast_sigmoid(v1 + bias[col + 1]);
                }
                if (hout) {
                    __half* op = (__half*)ga.outp[p];
                    *(__half2*)(op + (size_t)m * Hdim + col) =
                        __halves2half2(__float2half_rn(v0), __float2half_rn(v1));
                } else {
                    float* op = (float*)ga.outp[p];
                    *(float2*)(op + (size_t)m * Hdim + col) = make_float2(v0, v1);
                }
            }
        }
    }
}

// -------------------- vector helpers ---------------------------------------
__device__ __forceinline__ void unpack8(uint4 u, float* f) {
    __half2* h = (__half2*)&u;
#pragma unroll
    for (int q = 0; q < 4; q++) {
        float2 t = __half22float2(h[q]);
        f[2 * q] = t.x;
        f[2 * q + 1] = t.y;
    }
}
__device__ __forceinline__ uint4 pack8(const float* f) {
    uint4 u;
    __half2* h = (__half2*)&u;
#pragma unroll
    for (int q = 0; q < 4; q++)
        h[q] = __halves2half2(__float2half_rn(f[2 * q]), __float2half_rn(f[2 * q + 1]));
    return u;
}
__device__ __forceinline__ void ld8f(const float* p, float* f) {
    float4 u0 = *(const float4*)p;
    float4 u1 = *(const float4*)(p + 4);
    f[0] = u0.x; f[1] = u0.y; f[2] = u0.z; f[3] = u0.w;
    f[4] = u1.x; f[5] = u1.y; f[6] = u1.z; f[7] = u1.w;
}
__device__ __forceinline__ void st8f(float* p, const float* f) {
    *(float4*)p = make_float4(f[0], f[1], f[2], f[3]);
    *(float4*)(p + 4) = make_float4(f[4], f[5], f[6], f[7]);
}

// -------------------- hierarchical chunked scan -----------------------------
__global__ void scan_stage1(const void* __restrict__ mraw) {
    int id = blockIdx.x * blockDim.x + threadIdx.x;
    int h8 = (id & 127) * 8;
    int j  = (id >> 7) & (CHUNKS - 1);
    int b  = id >> 15;
    int mode = g_mask_mode;
    float A[8], Bc[8];
#pragma unroll
    for (int e = 0; e < 8; e++) { A[e] = 1.0f; Bc[e] = 0.0f; }
    size_t base = (size_t)b * Sdim * Hdim + h8;
    int s0 = j * CLEN;
#pragma unroll
    for (int t = 0; t < CLEN; t++) {
        int s = s0 + t;
        size_t idx = base + (size_t)s * Hdim;
        float a[8], w[8], c[8];
        unpack8(*(const uint4*)(g_ret + idx), a);
        unpack8(*(const uint4*)(g_wg + idx), w);
        unpack8(*(const uint4*)(g_cont + idx), c);
        float m = mask_at(mraw, b * Sdim + s, mode);
#pragma unroll
        for (int e = 0; e < 8; e++) {
            float aa = 1.0f + m * (a[e] - 1.0f);
            float bb = m * ((1.0f - a[e]) * w[e] * c[e]);
            A[e] *= aa;
            Bc[e] = fmaf(aa, Bc[e], bb);
        }
    }
    int cidx = (b * CHUNKS + j) * Hdim + h8;
    st8f(g_Ac + cidx, A);
    st8f(g_Bc + cidx, Bc);
}

__global__ void scan_stage2a() {
    int id = blockIdx.x * blockDim.x + threadIdx.x;
    int h8 = (id & 127) * 8;
    int sc = (id >> 7) & (NSUP - 1);
    int b  = id >> 11;
    float A[8], Bv[8];
#pragma unroll
    for (int e = 0; e < 8; e++) { A[e] = 1.0f; Bv[e] = 0.0f; }
#pragma unroll
    for (int c = 0; c < SUPC; c++) {
        int j = sc * SUPC + c;
        int cidx = (b * CHUNKS + j) * Hdim + h8;
        float Ac[8], Bc[8];
        ld8f(g_Ac + cidx, Ac);
        ld8f(g_Bc + cidx, Bc);
#pragma unroll
        for (int e = 0; e < 8; e++) {
            Bv[e] = fmaf(Ac[e], Bv[e], Bc[e]);
            A[e] *= Ac[e];
        }
    }
    int sidx = (b * NSUP + sc) * Hdim + h8;
    st8f(g_As + sidx, A);
    st8f(g_Bs + sidx, Bv);
}

__global__ void scan_stage2b(const float* __restrict__ state,
                             float* __restrict__ fs_out) {
    int id = blockIdx.x * blockDim.x + threadIdx.x;
    int h8 = (id & 127) * 8;
    int b  = id >> 7;
    float st[8];
    ld8f(state + b * Hdim + h8, st);
#pragma unroll
    for (int sc = 0; sc < NSUP; sc++) {
        int sidx = (b * NSUP + sc) * Hdim + h8;
        st8f(g_Sss + sidx, st);
        float A[8], Bv[8];
        ld8f(g_As + sidx, A);
        ld8f(g_Bs + sidx, Bv);
#pragma unroll
        for (int e = 0; e < 8; e++) st[e] = fmaf(A[e], st[e], Bv[e]);
    }
    st8f(fs_out + b * Hdim + h8, st);
}

__global__ void scan_stage2c() {
    int id = blockIdx.x * blockDim.x + threadIdx.x;
    int h8 = (id & 127) * 8;
    int sc = (id >> 7) & (NSUP - 1);
    int b  = id >> 11;
    float st[8];
    ld8f(g_Sss + (b * NSUP + sc) * Hdim + h8, st);
#pragma unroll
    for (int c = 0; c < SUPC; c++) {
        int j = sc * SUPC + c;
        int cidx = (b * CHUNKS + j) * Hdim + h8;
        st8f(g_Ss + cidx, st);
        float Ac[8], Bc[8];
        ld8f(g_Ac + cidx, Ac);
        ld8f(g_Bc + cidx, Bc);
#pragma unroll
        for (int e = 0; e < 8; e++) st[e] = fmaf(Ac[e], st[e], Bc[e]);
    }
}

__global__ void scan_stage3(const void* __restrict__ mraw) {
    int id = blockIdx.x * blockDim.x + threadIdx.x;
    int h8 = (id & 127) * 8;
    int j  = (id >> 7) & (CHUNKS - 1);
    int b  = id >> 15;
    int mode = g_mask_mode;
    float st[8];
    ld8f(g_Ss + (b * CHUNKS + j) * Hdim + h8, st);
    size_t base = (size_t)b * Sdim * Hdim + h8;
    int s0 = j * CLEN;
#pragma unroll
    for (int t = 0; t < CLEN; t++) {
        int s = s0 + t;
        size_t idx = base + (size_t)s * Hdim;
        float a[8], w[8], c[8], r[8], k[8], y[8];
        unpack8(*(const uint4*)(g_ret + idx), a);
        unpack8(*(const uint4*)(g_wg + idx), w);
        unpack8(*(const uint4*)(g_cont + idx), c);
        unpack8(*(const uint4*)(g_rg + idx), r);
        unpack8(*(const uint4*)(g_sk + idx), k);
        float m = mask_at(mraw, b * Sdim + s, mode);
#pragma unroll
        for (int e = 0; e < 8; e++) {
            float aa = 1.0f + m * (a[e] - 1.0f);
            float bb = m * ((1.0f - a[e]) * w[e] * c[e]);
            st[e] = fmaf(aa, st[e], bb);
            y[e] = m * fmaf(r[e], st[e], k[e]);
        }
        *(uint4*)(g_y1 + idx) = pack8(y);
    }
}

// -------------------- launch -----------------------------------------------
extern "C" void kernel_launch(void* const* d_in, const int* in_sizes, int n_in,
                              void* d_out, int out_size) {
    const float* x     = (const float*)d_in[0];
    const float* state = (const float*)d_in[1];
    const void*  mask  = d_in[2];
    const float* W_in  = (const float*)d_in[3];
    const float* W_a   = (const float*)d_in[4];
    const float* b_a   = (const float*)d_in[5];
    const float* W_b   = (const float*)d_in[6];
    const float* b_b   = (const float*)d_in[7];
    const float* W_c   = (const float*)d_in[8];
    const float* b_c   = (const float*)d_in[9];
    const float* W_d   = (const float*)d_in[10];
    const float* W_out = (const float*)d_in[11];
    float* out = (float*)d_out;

    __half *p_x1, *p_y1, *p_w51, *p_wo1, *p_cont, *p_ret, *p_wg, *p_rg, *p_sk;
    float *p_fsdummy;
    cudaGetSymbolAddress((void**)&p_x1,  g_x1);
    cudaGetSymbolAddress((void**)&p_y1,  g_y1);
    cudaGetSymbolAddress((void**)&p_w51, g_w51);
    cudaGetSymbolAddress((void**)&p_wo1, g_wo1);
    cudaGetSymbolAddress((void**)&p_cont, g_cont);
    cudaGetSymbolAddress((void**)&p_ret,  g_ret);
    cudaGetSymbolAddress((void**)&p_wg,   g_wg);
    cudaGetSymbolAddress((void**)&p_rg,   g_rg);
    cudaGetSymbolAddress((void**)&p_sk,   g_sk);
    cudaGetSymbolAddress((void**)&p_fsdummy, g_fs_dummy);

    cudaFuncSetAttribute(gemm_mma_kernel,
                         cudaFuncAttributeMaxDynamicSharedMemorySize, SMEM_TOTAL);

    // fused conversions (22 x 1M-elem jobs) + mask detection (last block)
    const size_t WN = (size_t)Hdim * Hdim;
    CvtAllArgs ca;
    for (int q = 0; q < 16; q++) {
        ca.src[q] = x + q * WN;
        ca.dst[q] = p_x1 + q * WN;
    }
    ca.src[16] = W_in;  ca.dst[16] = p_w51 + 0 * WN;
    ca.src[17] = W_a;   ca.dst[17] = p_w51 + 1 * WN;
    ca.src[18] = W_b;   ca.dst[18] = p_w51 + 2 * WN;
    ca.src[19] = W_c;   ca.dst[19] = p_w51 + 3 * WN;
    ca.src[20] = W_d;   ca.dst[20] = p_w51 + 4 * WN;
    ca.src[21] = W_out; ca.dst[21] = p_wo1;
    ca.mask = (const unsigned char*)mask;
    ca.mask_n = Mrows;
    cvt_all_kernel<<<22 * 1024 + 1, 256>>>(ca);

    // Phase 1: fused 5-projection GEMM
    GArgs g1;
    g1.A1 = p_x1; g1.W1 = p_w51;
    g1.outp[0] = p_cont; g1.outp[1] = p_ret; g1.outp[2] = p_wg;
    g1.outp[3] = p_rg;   g1.outp[4] = p_sk;
    g1.bias[0] = nullptr; g1.bias[1] = b_a; g1.bias[2] = b_b;
    g1.bias[3] = b_c;     g1.bias[4] = nullptr;
    g1.act[0] = 1; g1.act[1] = 2; g1.act[2] = 2; g1.act[3] = 2; g1.act[4] = 0;
    g1.half_out[0] = 1; g1.half_out[1] = 1; g1.half_out[2] = 1;
    g1.half_out[3] = 1; g1.half_out[4] = 1;
    gemm_mma_kernel<<<dim3(40, 128), 256, SMEM_TOTAL>>>(g1);

    // Phase 2: hierarchical chunked scan
    float* fsPtr = (out_size >= BSH + Bdim * Hdim) ? (out + BSH) : p_fsdummy;
    scan_stage1<<<512, 256>>>(mask);
    scan_stage2a<<<32, 256>>>();
    scan_stage2b<<<2, 256>>>(state, fsPtr);
    scan_stage2c<<<32, 256>>>();
    scan_stage3<<<512, 256>>>(mask);

    // Phase 3: output GEMM
    GArgs g2;
    g2.A1 = p_y1; g2.W1 = p_wo1;
    for (int i = 0; i < 5; i++) {
        g2.outp[i] = out; g2.bias[i] = nullptr; g2.act[i] = 0; g2.half_out[i] = 0;
    }
    gemm_mma_kernel<<<dim3(8, 128), 256, SMEM_TOTAL>>>(g2);
}

// round 15
// speedup vs baseline: 1.6278x; 1.0129x over previous
#include <cuda_runtime.h>
#include <cuda_bf16.h>
#include <cuda_fp16.h>
#include <math.h>
#include <stdint.h>

// ---------------------------------------------------------------------------
// Mamba2 block: single-product fp16 HMMA GEMMs (64x32 warp tiles, 256thr,
// 2 CTA/SM, 3-stage cp.async) + hierarchical scan with fused middle stage.
// ---------------------------------------------------------------------------

#define Bdim 4
#define Sdim 4096
#define Hdim 1024
#define Mrows (Bdim * Sdim)        // 16384
#define BSH   (Mrows * Hdim)
#define CHUNKS 256
#define CLEN   16
#define NSUP   16
#define SUPC   16

// -------------------- scratch (static __device__, no allocs) ---------------
__device__ __half g_x1[BSH];
__device__ __half g_y1[BSH];
__device__ __half g_w51[5 * Hdim * Hdim];
__device__ __half g_wo1[Hdim * Hdim];
__device__ __half g_cont[BSH];
__device__ __half g_ret[BSH];
__device__ __half g_wg[BSH];
__device__ __half g_rg[BSH];
__device__ __half g_sk[BSH];
__device__ float g_Ac[Bdim * CHUNKS * Hdim];
__device__ float g_Bc[Bdim * CHUNKS * Hdim];
__device__ float g_Ss[Bdim * CHUNKS * Hdim];
__device__ float g_As[Bdim * NSUP * Hdim];
__device__ float g_Bs[Bdim * NSUP * Hdim];
__device__ float g_Sss[Bdim * NSUP * Hdim];
__device__ int   g_mask_mode;
__device__ float g_fs_dummy[Bdim * Hdim];

// -------------------- fast activations (MUFU) -------------------------------
__device__ __forceinline__ float fast_ex2(float x) {
    float r;
    asm("ex2.approx.f32 %0, %1;" : "=f"(r) : "f"(x));
    return r;
}
__device__ __forceinline__ float fast_rcp(float x) {
    float r;
    asm("rcp.approx.f32 %0, %1;" : "=f"(r) : "f"(x));
    return r;
}
#define L2E 1.4426950408889634f
__device__ __forceinline__ float fast_sigmoid(float x) {
    return fast_rcp(1.0f + fast_ex2(-L2E * x));
}
__device__ __forceinline__ float fast_tanh(float x) {
    float xc = fminf(fmaxf(x, -10.0f), 10.0f);
    float t = fast_ex2(2.0f * L2E * xc);
    return (t - 1.0f) * fast_rcp(t + 1.0f);
}

__device__ __forceinline__ float mask_at(const void* mraw, int i, int mode) {
    if (mode == 1) return ((const int*)mraw)[i] != 0 ? 1.0f : 0.0f;
    if (mode == 2) return ((const float*)mraw)[i] != 0.0f ? 1.0f : 0.0f;
    return ((const unsigned char*)mraw)[i] ? 1.0f : 0.0f;
}

// -------------------- fused conversions + mask detection --------------------
struct CvtAllArgs {
    const float* src[22];
    __half* dst[22];
    const unsigned char* mask;
    int mask_n;
};
__global__ void cvt_all_kernel(CvtAllArgs a) {
    if (blockIdx.x == 22 * 1024) {
        __shared__ int cflag[4];
        int t = threadIdx.x;
        if (t < 4) cflag[t] = 0;
        __syncthreads();
        for (int i = t; i < a.mask_n; i += blockDim.x)
            if (a.mask[i]) atomicOr(&cflag[i & 3], 1);
        __syncthreads();
        if (t == 0) {
            int c0 = cflag[0], c1 = cflag[1], c2 = cflag[2], c3 = cflag[3];
            int mode = 0;
            if (c0 | c1 | c2 | c3) {
                if (c0 && !c1 && !c2 && !c3) mode = 1;
                else if (!c0 && !c1 && (c2 | c3)) mode = 2;
            }
            g_mask_mode = mode;
        }
        return;
    }
    int job = blockIdx.x >> 10;
    int i = ((blockIdx.x & 1023) * blockDim.x + threadIdx.x) * 4;
    const float* in = a.src[job];
    __half* o = a.dst[job];
    float4 v = *(const float4*)(in + i);
    ((__half2*)(o + i))[0] = __halves2half2(__float2half_rn(v.x), __float2half_rn(v.y));
    ((__half2*)(o + i))[1] = __halves2half2(__float2half_rn(v.z), __float2half_rn(v.w));
}

// -------------------- PTX helpers ------------------------------------------
__device__ __forceinline__ uint32_t su32(const void* p) {
    uint32_t a;
    asm("{ .reg .u64 t; cvta.to.shared.u64 t, %1; cvt.u32.u64 %0, t; }"
        : "=r"(a) : "l"(p));
    return a;
}
__device__ __forceinline__ void cpa16(uint32_t s, const void* g) {
    asm volatile("cp.async.cg.shared.global [%0], [%1], 16;" :: "r"(s), "l"(g));
}
__device__ __forceinline__ void cpa_commit() {
    asm volatile("cp.async.commit_group;" ::: "memory");
}
__device__ __forceinline__ void cpa_wait1() {
    asm volatile("cp.async.wait_group 1;" ::: "memory");
}
__device__ __forceinline__ void cpa_wait0() {
    asm volatile("cp.async.wait_group 0;" ::: "memory");
}
__device__ __forceinline__ void ldm_x4(uint32_t* r, uint32_t addr) {
    asm volatile("ldmatrix.sync.aligned.m8n8.x4.shared.b16 {%0,%1,%2,%3}, [%4];"
                 : "=r"(r[0]), "=r"(r[1]), "=r"(r[2]), "=r"(r[3]) : "r"(addr));
}
__device__ __forceinline__ void mma_f16(float* d, const uint32_t* a,
                                        const uint32_t* b) {
    asm volatile(
        "mma.sync.aligned.m16n8k16.row.col.f32.f16.f16.f32 "
        "{%0,%1,%2,%3}, {%4,%5,%6,%7}, {%8,%9}, {%0,%1,%2,%3};"
        : "+f"(d[0]), "+f"(d[1]), "+f"(d[2]), "+f"(d[3])
        : "r"(a[0]), "r"(a[1]), "r"(a[2]), "r"(a[3]), "r"(b[0]), "r"(b[1]));
}

// -------------------- GEMM: 64x32 warp tiles, 256 threads, 2 CTA/SM ---------
#define TILE_BYTES 16384
#define STAGE_BYTES 32768
#define SMEM_TOTAL (3 * STAGE_BYTES)   // 98304
#define NSTAGES (Hdim / 64)            // 16

struct GArgs {
    const __half *A1, *W1;
    void*        outp[5];
    const float* bias[5];
    int          act[5];
    int          half_out[5];
};

__device__ __forceinline__ uint32_t sw128(uint32_t base, int row, int chunk) {
    return base + row * 128 + ((chunk ^ (row & 7)) << 4);
}

__global__ __launch_bounds__(256, 2)
void gemm_mma_kernel(GArgs ga) {
    extern __shared__ char smem[];
    uint32_t sb = su32(smem);
    int tid = threadIdx.x;
    int wid = tid >> 5, lane = tid & 31;
    int wm = wid >> 2, wn = wid & 3;           // 2 x 4 warp grid
    int m0 = wm * 64, n0 = wn * 32;            // warp tile 64x32

    int mBase = blockIdx.y * 128;
    int nBase = blockIdx.x * 128;
    const __half* pA = ga.A1 + (size_t)mBase * Hdim;
    const __half* pW = ga.W1 + (size_t)nBase * Hdim;

    float acc[4][4][4];
#pragma unroll
    for (int i = 0; i < 4; i++)
#pragma unroll
        for (int j = 0; j < 4; j++)
#pragma unroll
            for (int e = 0; e < 4; e++) acc[i][j][e] = 0.0f;

    auto load_stage = [&](int s) {
        uint32_t so = sb + (s % 3) * STAGE_BYTES;
        int k0 = s * 64;
#pragma unroll
        for (int i = 0; i < 8; i++) {
            int c = tid + i * 256;
            int T = c >> 10;
            int ct = c & 1023;
            int row = ct >> 3, col = ct & 7;
            const __half* src = T ? pW : pA;
            cpa16(sw128(so + T * TILE_BYTES, row, col),
                  src + (size_t)row * Hdim + k0 + col * 8);
        }
        cpa_commit();
    };

    load_stage(0);
    load_stage(1);

    int aRow = (lane & 15);
    int aKC  = (lane >> 4);
    int bRow = (lane & 7) + ((lane >> 4) << 3);
    int bKC  = (lane >> 3) & 1;

    for (int s = 0; s < NSTAGES; s++) {
        if (s + 1 < NSTAGES) cpa_wait1();
        else cpa_wait0();
        __syncthreads();
        if (s + 2 < NSTAGES) load_stage(s + 2);

        uint32_t so = sb + (s % 3) * STAGE_BYTES;
        uint32_t tA = so;
        uint32_t tW = so + TILE_BYTES;

#pragma unroll
        for (int kk = 0; kk < 4; kk++) {
            int kc = kk * 2;
            uint32_t b1[8];
#pragma unroll
            for (int half = 0; half < 2; half++)
                ldm_x4(b1 + half * 4, sw128(tW, n0 + half * 16 + bRow, kc + bKC));
#pragma unroll
            for (int mf = 0; mf < 4; mf++) {
                uint32_t a[4];
                ldm_x4(a, sw128(tA, m0 + mf * 16 + aRow, kc + aKC));
#pragma unroll
                for (int nf = 0; nf < 4; nf++)
                    mma_f16(acc[mf][nf], a, b1 + (nf >> 1) * 4 + (nf & 1) * 2);
            }
        }
    }

    int p = nBase >> 10;
    const float* __restrict__ bias = ga.bias[p];
    int act = ga.act[p];
    int hout = ga.half_out[p];
    int ocol0 = (nBase & 1023) + n0;

#pragma unroll
    for (int mf = 0; mf < 4; mf++) {
#pragma unroll
        for (int rh = 0; rh < 2; rh++) {
            int m = mBase + m0 + mf * 16 + (lane >> 2) + rh * 8;
#pragma unroll
            for (int nf = 0; nf < 4; nf++) {
                int col = ocol0 + nf * 8 + (lane & 3) * 2;
                float v0 = acc[mf][nf][rh * 2 + 0];
                float v1 = acc[mf][nf][rh * 2 + 1];
                if (act == 1) {
                    v0 = fast_tanh(v0);
                    v1 = fast_tanh(v1);
                } else if (act == 2) {
                    v0 = fast_sigmoid(v0 + bias[col]);
                    v1 = fast_sigmoid(v1 + bias[col + 1]);
                }
                if (hout) {
                    __half* op = (__half*)ga.outp[p];
                    *(__half2*)(op + (size_t)m * Hdim + col) =
                        __halves2half2(__float2half_rn(v0), __float2half_rn(v1));
                } else {
                    float* op = (float*)ga.outp[p];
                    *(float2*)(op + (size_t)m * Hdim + col) = make_float2(v0, v1);
                }
            }
        }
    }
}

// -------------------- vector helpers ---------------------------------------
__device__ __forceinline__ void unpack8(uint4 u, float* f) {
    __half2* h = (__half2*)&u;
#pragma unroll
    for (int q = 0; q < 4; q++) {
        float2 t = __half22float2(h[q]);
        f[2 * q] = t.x;
        f[2 * q + 1] = t.y;
    }
}
__device__ __forceinline__ uint4 pack8(const float* f) {
    uint4 u;
    __half2* h = (__half2*)&u;
#pragma unroll
    for (int q = 0; q < 4; q++)
        h[q] = __halves2half2(__float2half_rn(f[2 * q]), __float2half_rn(f[2 * q + 1]));
    return u;
}
__device__ __forceinline__ void ld8f(const float* p, float* f) {
    float4 u0 = *(const float4*)p;
    float4 u1 = *(const float4*)(p + 4);
    f[0] = u0.x; f[1] = u0.y; f[2] = u0.z; f[3] = u0.w;
    f[4] = u1.x; f[5] = u1.y; f[6] = u1.z; f[7] = u1.w;
}
__device__ __forceinline__ void st8f(float* p, const float* f) {
    *(float4*)p = make_float4(f[0], f[1], f[2], f[3]);
    *(float4*)(p + 4) = make_float4(f[4], f[5], f[6], f[7]);
}

// -------------------- hierarchical chunked scan -----------------------------
__global__ void scan_stage1(const void* __restrict__ mraw) {
    int id = blockIdx.x * blockDim.x + threadIdx.x;
    int h8 = (id & 127) * 8;
    int j  = (id >> 7) & (CHUNKS - 1);
    int b  = id >> 15;
    int mode = g_mask_mode;
    float A[8], Bc[8];
#pragma unroll
    for (int e = 0; e < 8; e++) { A[e] = 1.0f; Bc[e] = 0.0f; }
    size_t base = (size_t)b * Sdim * Hdim + h8;
    int s0 = j * CLEN;
#pragma unroll
    for (int t = 0; t < CLEN; t++) {
        int s = s0 + t;
        size_t idx = base + (size_t)s * Hdim;
        float a[8], w[8], c[8];
        unpack8(*(const uint4*)(g_ret + idx), a);
        unpack8(*(const uint4*)(g_wg + idx), w);
        unpack8(*(const uint4*)(g_cont + idx), c);
        float m = mask_at(mraw, b * Sdim + s, mode);
#pragma unroll
        for (int e = 0; e < 8; e++) {
            float aa = 1.0f + m * (a[e] - 1.0f);
            float bb = m * ((1.0f - a[e]) * w[e] * c[e]);
            A[e] *= aa;
            Bc[e] = fmaf(aa, Bc[e], bb);
        }
    }
    int cidx = (b * CHUNKS + j) * Hdim + h8;
    st8f(g_Ac + cidx, A);
    st8f(g_Bc + cidx, Bc);
}

// Fused middle stage: per block = (batch, slice of 16 h8-slots).
//  A: compose 16 chunk summaries -> superchunk summaries  (256 tasks)
//  B: scan 16 superchunks from initial state               (16 threads)
//  C: expand chunk-start states within superchunks         (256 tasks)
__global__ void scan_stage2_fused(const float* __restrict__ state,
                                  float* __restrict__ fs_out) {
    int b     = blockIdx.x >> 3;         // 0..3
    int slice = blockIdx.x & 7;          // 0..7 (16 h8-slots each)
    int tid = threadIdx.x;

    // Phase A
    {
        int sc   = tid >> 4;             // 0..15
        int slot = tid & 15;             // 0..15
        int h8 = (slice * 16 + slot) * 8;
        float A[8], Bv[8];
#pragma unroll
        for (int e = 0; e < 8; e++) { A[e] = 1.0f; Bv[e] = 0.0f; }
#pragma unroll
        for (int c = 0; c < SUPC; c++) {
            int j = sc * SUPC + c;
            int cidx = (b * CHUNKS + j) * Hdim + h8;
            float Ac[8], Bc[8];
            ld8f(g_Ac + cidx, Ac);
            ld8f(g_Bc + cidx, Bc);
#pragma unroll
            for (int e = 0; e < 8; e++) {
                Bv[e] = fmaf(Ac[e], Bv[e], Bc[e]);
                A[e] *= Ac[e];
            }
        }
        int sidx = (b * NSUP + sc) * Hdim + h8;
        st8f(g_As + sidx, A);
        st8f(g_Bs + sidx, Bv);
    }
    __syncthreads();

    // Phase B (16 threads, one per h8-slot in the slice)
    if (tid < 16) {
        int h8 = (slice * 16 + tid) * 8;
        float st[8];
        ld8f(state + b * Hdim + h8, st);
#pragma unroll
        for (int sc = 0; sc < NSUP; sc++) {
            int sidx = (b * NSUP + sc) * Hdim + h8;
            st8f(g_Sss + sidx, st);
            float A[8], Bv[8];
            ld8f(g_As + sidx, A);
            ld8f(g_Bs + sidx, Bv);
#pragma unroll
            for (int e = 0; e < 8; e++) st[e] = fmaf(A[e], st[e], Bv[e]);
        }
        st8f(fs_out + b * Hdim + h8, st);
    }
    __syncthreads();

    // Phase C
    {
        int sc   = tid >> 4;
        int slot = tid & 15;
        int h8 = (slice * 16 + slot) * 8;
        float st[8];
        ld8f(g_Sss + (b * NSUP + sc) * Hdim + h8, st);
#pragma unroll
        for (int c = 0; c < SUPC; c++) {
            int j = sc * SUPC + c;
            int cidx = (b * CHUNKS + j) * Hdim + h8;
            st8f(g_Ss + cidx, st);
            float Ac[8], Bc[8];
            ld8f(g_Ac + cidx, Ac);
            ld8f(g_Bc + cidx, Bc);
#pragma unroll
            for (int e = 0; e < 8; e++) st[e] = fmaf(Ac[e], st[e], Bc[e]);
        }
    }
}

__global__ void scan_stage3(const void* __restrict__ mraw) {
    int id = blockIdx.x * blockDim.x + threadIdx.x;
    int h8 = (id & 127) * 8;
    int j  = (id >> 7) & (CHUNKS - 1);
    int b  = id >> 15;
    int mode = g_mask_mode;
    float st[8];
    ld8f(g_Ss + (b * CHUNKS + j) * Hdim + h8, st);
    size_t base = (size_t)b * Sdim * Hdim + h8;
    int s0 = j * CLEN;
#pragma unroll
    for (int t = 0; t < CLEN; t++) {
        int s = s0 + t;
        size_t idx = base + (size_t)s * Hdim;
        float a[8], w[8], c[8], r[8], k[8], y[8];
        unpack8(*(const uint4*)(g_ret + idx), a);
        unpack8(*(const uint4*)(g_wg + idx), w);
        unpack8(*(const uint4*)(g_cont + idx), c);
        unpack8(*(const uint4*)(g_rg + idx), r);
        unpack8(*(const uint4*)(g_sk + idx), k);
        float m = mask_at(mraw, b * Sdim + s, mode);
#pragma unroll
        for (int e = 0; e < 8; e++) {
            float aa = 1.0f + m * (a[e] - 1.0f);
            float bb = m * ((1.0f - a[e]) * w[e] * c[e]);
            st[e] = fmaf(aa, st[e], bb);
            y[e] = m * fmaf(r[e], st[e], k[e]);
        }
        *(uint4*)(g_y1 + idx) = pack8(y);
    }
}

// -------------------- launch -----------------------------------------------
extern "C" void kernel_launch(void* const* d_in, const int* in_sizes, int n_in,
                              void* d_out, int out_size) {
    const float* x     = (const float*)d_in[0];
    const float* state = (const float*)d_in[1];
    const void*  mask  = d_in[2];
    const float* W_in  = (const float*)d_in[3];
    const float* W_a   = (const float*)d_in[4];
    const float* b_a   = (const float*)d_in[5];
    const float* W_b   = (const float*)d_in[6];
    const float* b_b   = (const float*)d_in[7];
    const float* W_c   = (const float*)d_in[8];
    const float* b_c   = (const float*)d_in[9];
    const float* W_d   = (const float*)d_in[10];
    const float* W_out = (const float*)d_in[11];
    float* out = (float*)d_out;

    __half *p_x1, *p_y1, *p_w51, *p_wo1, *p_cont, *p_ret, *p_wg, *p_rg, *p_sk;
    float *p_fsdummy;
    cudaGetSymbolAddress((void**)&p_x1,  g_x1);
    cudaGetSymbolAddress((void**)&p_y1,  g_y1);
    cudaGetSymbolAddress((void**)&p_w51, g_w51);
    cudaGetSymbolAddress((void**)&p_wo1, g_wo1);
    cudaGetSymbolAddress((void**)&p_cont, g_cont);
    cudaGetSymbolAddress((void**)&p_ret,  g_ret);
    cudaGetSymbolAddress((void**)&p_wg,   g_wg);
    cudaGetSymbolAddress((void**)&p_rg,   g_rg);
    cudaGetSymbolAddress((void**)&p_sk,   g_sk);
    cudaGetSymbolAddress((void**)&p_fsdummy, g_fs_dummy);

    cudaFuncSetAttribute(gemm_mma_kernel,
                         cudaFuncAttributeMaxDynamicSharedMemorySize, SMEM_TOTAL);

    // fused conversions (22 x 1M-elem jobs) + mask detection (last block)
    const size_t WN = (size_t)Hdim * Hdim;
    CvtAllArgs ca;
    for (int q = 0; q < 16; q++) {
        ca.src[q] = x + q * WN;
        ca.dst[q] = p_x1 + q * WN;
    }
    ca.src[16] = W_in;  ca.dst[16] = p_w51 + 0 * WN;
    ca.src[17] = W_a;   ca.dst[17] = p_w51 + 1 * WN;
    ca.src[18] = W_b;   ca.dst[18] = p_w51 + 2 * WN;
    ca.src[19] = W_c;   ca.dst[19] = p_w51 + 3 * WN;
    ca.src[20] = W_d;   ca.dst[20] = p_w51 + 4 * WN;
    ca.src[21] = W_out; ca.dst[21] = p_wo1;
    ca.mask = (const unsigned char*)mask;
    ca.mask_n = Mrows;
    cvt_all_kernel<<<22 * 1024 + 1, 256>>>(ca);

    // Phase 1: fused 5-projection GEMM
    GArgs g1;
    g1.A1 = p_x1; g1.W1 = p_w51;
    g1.outp[0] = p_cont; g1.outp[1] = p_ret; g1.outp[2] = p_wg;
    g1.outp[3] = p_rg;   g1.outp[4] = p_sk;
    g1.bias[0] = nullptr; g1.bias[1] = b_a; g1.bias[2] = b_b;
    g1.bias[3] = b_c;     g1.bias[4] = nullptr;
    g1.act[0] = 1; g1.act[1] = 2; g1.act[2] = 2; g1.act[3] = 2; g1.act[4] = 0;
    g1.half_out[0] = 1; g1.half_out[1] = 1; g1.half_out[2] = 1;
    g1.half_out[3] = 1; g1.half_out[4] = 1;
    gemm_mma_kernel<<<dim3(40, 128), 256, SMEM_TOTAL>>>(g1);

    // Phase 2: hierarchical chunked scan (stage2 fused into one kernel)
    float* fsPtr = (out_size >= BSH + Bdim * Hdim) ? (out + BSH) : p_fsdummy;
    scan_stage1<<<512, 256>>>(mask);
    scan_stage2_fused<<<32, 256>>>(state, fsPtr);
    scan_stage3<<<512, 256>>>(mask);

    // Phase 3: output GEMM
    GArgs g2;
    g2.A1 = p_y1; g2.W1 = p_wo1;
    for (int i = 0; i < 5; i++) {
        g2.outp[i] = out; g2.bias[i] = nullptr; g2.act[i] = 0; g2.half_out[i] = 0;
    }
    gemm_mma_kernel<<<dim3(8, 128), 256, SMEM_TOTAL>>>(g2);
}